// round 5
// baseline (speedup 1.0000x reference)
#include <cuda_runtime.h>
#include <cuda_fp16.h>
#include <cstdint>

// ---------------- problem dims (fixed) ----------------
#define B_DIM   1024
#define IN_DIM  4096
#define OUT_DIM 4096
#define NB      1024          // IN_DIM / 4 quant blocks per row
#define NX_BLOCKS (B_DIM * NB)      // 1,048,576  (x quant blocks)
#define NW_BLOCKS (OUT_DIM * NB)    // 4,194,304  (w quant blocks)
#define NT_BLOCKS (NX_BLOCKS + NW_BLOCKS)

// ---------------- GEMM tiling ----------------
#define BM 128
#define BN 128
#define BK 64                 // fp16: 128 bytes per smem row
#define NCHUNK (IN_DIM / BK)  // 64
#define STAGES 3
#define A_BYTES (BM * 128)                    // 16 KB
#define B_BYTES (BN * 128)                    // 16 KB
#define STAGE_BYTES (A_BYTES + B_BYTES)       // 32 KB
#define SMEM_TOTAL (STAGES * STAGE_BYTES)     // 96 KB -> 2 CTAs/SM

// ---------------- fp16 dequant scratch (device globals: allocation-free) ----------------
__device__ __half g_Xh[(size_t)B_DIM * IN_DIM];    // 8 MB
__device__ __half g_Wh[(size_t)OUT_DIM * IN_DIM];  // 32 MB

// ---------------- helpers ----------------
__device__ __forceinline__ uint32_t smem_u32(const void* p) {
    uint32_t a;
    asm("{ .reg .u64 t; cvta.to.shared.u64 t, %1; cvt.u32.u64 %0, t; }" : "=r"(a) : "l"(p));
    return a;
}

__device__ __forceinline__ void cp_async16(uint32_t dst, const void* src) {
    asm volatile("cp.async.cg.shared.global [%0], [%1], 16;" :: "r"(dst), "l"(src) : "memory");
}
#define CP_COMMIT() asm volatile("cp.async.commit_group;" ::: "memory")
#define CP_WAIT(n)  asm volatile("cp.async.wait_group %0;" :: "n"(n) : "memory")

__device__ __forceinline__ void ldmatrix_x4(uint32_t& r0, uint32_t& r1, uint32_t& r2, uint32_t& r3,
                                            uint32_t addr) {
    asm volatile("ldmatrix.sync.aligned.m8n8.x4.shared.b16 {%0,%1,%2,%3}, [%4];"
                 : "=r"(r0), "=r"(r1), "=r"(r2), "=r"(r3) : "r"(addr));
}

__device__ __forceinline__ void mma16816(float* d, const uint32_t* a, const uint32_t* b) {
    asm volatile(
        "mma.sync.aligned.m16n8k16.row.col.f32.f16.f16.f32 "
        "{%0,%1,%2,%3}, {%4,%5,%6,%7}, {%8,%9}, {%0,%1,%2,%3};"
        : "+f"(d[0]), "+f"(d[1]), "+f"(d[2]), "+f"(d[3])
        : "r"(a[0]), "r"(a[1]), "r"(a[2]), "r"(a[3]), "r"(b[0]), "r"(b[1]));
}

// swizzled smem byte offset for (row, 16B-chunk)
__device__ __forceinline__ uint32_t swz(int row, int ch) {
    return (uint32_t)(row * 128 + ((ch ^ (row & 7)) << 4));
}

// ---------------- dequant (exact fp32 fake-quant, round to fp16) ----------------
__device__ __forceinline__ float fq(float v, float s, float z) {
    float q = rintf(v / s + z);             // round half-to-even, matches jnp.round
    q = fminf(fmaxf(q, 0.0f), 255.0f);
    return (q - z) * s;
}

union HalfPack { __half2 h2[2]; uint2 u; };

// Merged dequant: 8 quant blocks/thread, all loads issued before math (MLP ~16-24).
#define DQ_THREADS 256
#define DQ_PER_THREAD 8
#define DQ_PER_CTA (DQ_THREADS * DQ_PER_THREAD)   // 2048

__global__ void __launch_bounds__(DQ_THREADS, 4)
dequant_all_kernel(const float* __restrict__ x,  const float* __restrict__ xs,
                   const float* __restrict__ xz,
                   const float* __restrict__ w,  const float* __restrict__ ws,
                   const float* __restrict__ wz) {
    int j0 = blockIdx.x * DQ_PER_CTA + threadIdx.x;
    float4 v[DQ_PER_THREAD];
    float  s[DQ_PER_THREAD], z[DQ_PER_THREAD];

    if (j0 < NX_BLOCKS) {
#pragma unroll
        for (int u = 0; u < DQ_PER_THREAD; u++) {
            int j = j0 + u * DQ_THREADS;
            v[u] = reinterpret_cast<const float4*>(x)[j];
            int blk = j & (NB - 1);
            s[u] = __ldg(xs + blk);
            z[u] = __ldg(xz + blk);
        }
#pragma unroll
        for (int u = 0; u < DQ_PER_THREAD; u++) {
            HalfPack p;
            p.h2[0] = __floats2half2_rn(fq(v[u].x, s[u], z[u]), fq(v[u].y, s[u], z[u]));
            p.h2[1] = __floats2half2_rn(fq(v[u].z, s[u], z[u]), fq(v[u].w, s[u], z[u]));
            reinterpret_cast<uint2*>(g_Xh)[j0 + u * DQ_THREADS] = p.u;
        }
    } else {
        int k0 = j0 - NX_BLOCKS;
#pragma unroll
        for (int u = 0; u < DQ_PER_THREAD; u++) {
            int k = k0 + u * DQ_THREADS;
            v[u] = reinterpret_cast<const float4*>(w)[k];
            s[u] = __ldg(ws + k);
            z[u] = __ldg(wz + k);
        }
#pragma unroll
        for (int u = 0; u < DQ_PER_THREAD; u++) {
            HalfPack p;
            p.h2[0] = __floats2half2_rn(fq(v[u].x, s[u], z[u]), fq(v[u].y, s[u], z[u]));
            p.h2[1] = __floats2half2_rn(fq(v[u].z, s[u], z[u]), fq(v[u].w, s[u], z[u]));
            reinterpret_cast<uint2*>(g_Wh)[k0 + u * DQ_THREADS] = p.u;
        }
    }
}

// ---------------- stage loader: gmem(fp16) -> smem, 16B cp.async, swizzled ----------------
__device__ __forceinline__ void load_stage(uint32_t sA, uint32_t sB, int m0, int n0, int kc) {
    int t = threadIdx.x;
#pragma unroll
    for (int i = 0; i < 4; i++) {                  // A: 128 rows x 8 chunks = 1024
        int idx = t + i * 256;
        int row = idx >> 3, ch = idx & 7;
        const __half* src = g_Xh + (size_t)(m0 + row) * IN_DIM + kc + ch * 8;
        cp_async16(sA + swz(row, ch), src);
    }
#pragma unroll
    for (int i = 0; i < 4; i++) {                  // B: 128 rows x 8 chunks = 1024
        int idx = t + i * 256;
        int row = idx >> 3, ch = idx & 7;
        const __half* src = g_Wh + (size_t)(n0 + row) * IN_DIM + kc + ch * 8;
        cp_async16(sB + swz(row, ch), src);
    }
}

// ---------------- GEMM: 128x128 tile/CTA, warp tile 64x32, 3-stage, 2 CTAs/SM ----------------
__global__ void __launch_bounds__(256, 2)
gemm_f16_kernel(const float* __restrict__ bias, float* __restrict__ out) {
    extern __shared__ char smem[];
    uint32_t sbase = smem_u32(smem);
    int tid = threadIdx.x;
    int wid = tid >> 5, lane = tid & 31;
    int m0 = blockIdx.y * BM;
    int n0 = blockIdx.x * BN;
    int wm = (wid & 1) * 64;      // 2 (m) x 4 (n) warps, warp tile 64 x 32
    int wn = (wid >> 1) * 32;

    int lrow = lane & 15;         // ldmatrix x4: lanes 0-15 rows, 16-31 chunk+1
    int lch  = lane >> 4;

    float acc[4][4][4];
#pragma unroll
    for (int i = 0; i < 4; i++)
#pragma unroll
        for (int j = 0; j < 4; j++)
#pragma unroll
            for (int k = 0; k < 4; k++) acc[i][j][k] = 0.0f;

    // prologue: stages 0,1
#pragma unroll
    for (int st = 0; st < 2; st++) {
        load_stage(sbase + st * STAGE_BYTES, sbase + st * STAGE_BYTES + A_BYTES,
                   m0, n0, st * BK);
        CP_COMMIT();
    }

#pragma unroll 1
    for (int c = 0; c < NCHUNK; ++c) {
        CP_WAIT(1);               // stage c complete (c+1 may be in flight)
        __syncthreads();          // all warps done with slot (c-1)%3; stage c visible

        if (c + 2 < NCHUNK) {     // prefetch into slot (c+2)%3 == (c-1)%3
            int st = (c + 2) % STAGES;
            load_stage(sbase + st * STAGE_BYTES, sbase + st * STAGE_BYTES + A_BYTES,
                       m0, n0, (c + 2) * BK);
        }
        CP_COMMIT();

        uint32_t sA = sbase + (c % STAGES) * STAGE_BYTES;
        uint32_t sB = sA + A_BYTES;

#pragma unroll
        for (int ks = 0; ks < 4; ks++) {          // 4 x k16 per BK=64
            uint32_t a[4][4];
#pragma unroll
            for (int i = 0; i < 4; i++) {
                int row = wm + i * 16 + lrow;
                ldmatrix_x4(a[i][0], a[i][1], a[i][2], a[i][3],
                            sA + swz(row, ks * 2 + lch));
            }
            uint32_t b[4][2];
#pragma unroll
            for (int j = 0; j < 2; j++) {
                int row = wn + j * 16 + lrow;
                uint32_t r0, r1, r2, r3;
                ldmatrix_x4(r0, r1, r2, r3, sB + swz(row, ks * 2 + lch));
                b[2 * j][0] = r0;     b[2 * j][1] = r2;      // n-tile rows +0..7
                b[2 * j + 1][0] = r1; b[2 * j + 1][1] = r3;  // n-tile rows +8..15
            }
#pragma unroll
            for (int i = 0; i < 4; i++)
#pragma unroll
                for (int j = 0; j < 4; j++)
                    mma16816(acc[i][j], a[i], b[j]);
        }
    }

    // epilogue: C frag -> gmem with bias. lane: g = lane/4 (row), c2 = (lane%4)*2 (col)
    int g = lane >> 2, c2 = (lane & 3) * 2;
#pragma unroll
    for (int i = 0; i < 4; i++) {
        int row = m0 + wm + i * 16 + g;
        float* r0p = out + (size_t)row * OUT_DIM;
        float* r1p = out + (size_t)(row + 8) * OUT_DIM;
#pragma unroll
        for (int j = 0; j < 4; j++) {
            int col = n0 + wn + j * 8 + c2;
            float b0 = __ldg(&bias[col]), b1 = __ldg(&bias[col + 1]);
            float2 v0 = make_float2(acc[i][j][0] + b0, acc[i][j][1] + b1);
            float2 v1 = make_float2(acc[i][j][2] + b0, acc[i][j][3] + b1);
            *reinterpret_cast<float2*>(r0p + col) = v0;
            *reinterpret_cast<float2*>(r1p + col) = v1;
        }
    }
}

// ---------------- launch ----------------
extern "C" void kernel_launch(void* const* d_in, const int* in_sizes, int n_in,
                              void* d_out, int out_size) {
    const float* x    = (const float*)d_in[0];
    const float* w    = (const float*)d_in[1];
    const float* bias = (const float*)d_in[2];
    const float* ws   = (const float*)d_in[3];
    const float* wz   = (const float*)d_in[4];
    const float* as_  = (const float*)d_in[5];
    const float* az   = (const float*)d_in[6];
    float* out = (float*)d_out;

    dequant_all_kernel<<<NT_BLOCKS / DQ_PER_CTA, DQ_THREADS>>>(x, as_, az, w, ws, wz);

    cudaFuncSetAttribute(gemm_f16_kernel, cudaFuncAttributeMaxDynamicSharedMemorySize, SMEM_TOTAL);
    dim3 grid(OUT_DIM / BN, B_DIM / BM);   // 32 x 8 = 256 CTAs, one wave at occ 2
    gemm_f16_kernel<<<grid, 256, SMEM_TOTAL>>>(bias, out);
}

// round 6
// speedup vs baseline: 1.0502x; 1.0502x over previous
#include <cuda_runtime.h>
#include <cuda_fp16.h>
#include <cstdint>

// ---------------- problem dims (fixed) ----------------
#define B_DIM   1024
#define IN_DIM  4096
#define OUT_DIM 4096
#define NB      1024          // IN_DIM / 4 quant blocks per row
#define NX_BLOCKS (B_DIM * NB)      // 1,048,576  (x quant blocks)
#define NW_BLOCKS (OUT_DIM * NB)    // 4,194,304  (w quant blocks)
#define NT_BLOCKS (NX_BLOCKS + NW_BLOCKS)

// ---------------- GEMM tiling (R4 config: best measured) ----------------
#define BM 128
#define BN 256
#define BK 64                 // fp16: 128 bytes per smem row
#define NCHUNK (IN_DIM / BK)  // 64
#define STAGES 4
#define A_BYTES (BM * 128)                    // 16 KB
#define B_BYTES (BN * 128)                    // 32 KB
#define STAGE_BYTES (A_BYTES + B_BYTES)       // 48 KB
#define SMEM_TOTAL (STAGES * STAGE_BYTES)     // 192 KB

// ---------------- fp16 dequant scratch (device globals: allocation-free) ----------------
__device__ __half g_Xh[(size_t)B_DIM * IN_DIM];    // 8 MB
__device__ __half g_Wh[(size_t)OUT_DIM * IN_DIM];  // 32 MB

// ---------------- helpers ----------------
__device__ __forceinline__ uint32_t smem_u32(const void* p) {
    uint32_t a;
    asm("{ .reg .u64 t; cvta.to.shared.u64 t, %1; cvt.u32.u64 %0, t; }" : "=r"(a) : "l"(p));
    return a;
}

__device__ __forceinline__ void cp_async16(uint32_t dst, const void* src) {
    asm volatile("cp.async.cg.shared.global [%0], [%1], 16;" :: "r"(dst), "l"(src) : "memory");
}
#define CP_COMMIT() asm volatile("cp.async.commit_group;" ::: "memory")
#define CP_WAIT(n)  asm volatile("cp.async.wait_group %0;" :: "n"(n) : "memory")

__device__ __forceinline__ void ldmatrix_x4(uint32_t& r0, uint32_t& r1, uint32_t& r2, uint32_t& r3,
                                            uint32_t addr) {
    asm volatile("ldmatrix.sync.aligned.m8n8.x4.shared.b16 {%0,%1,%2,%3}, [%4];"
                 : "=r"(r0), "=r"(r1), "=r"(r2), "=r"(r3) : "r"(addr));
}

__device__ __forceinline__ void mma16816(float* d, const uint32_t* a, const uint32_t* b) {
    asm volatile(
        "mma.sync.aligned.m16n8k16.row.col.f32.f16.f16.f32 "
        "{%0,%1,%2,%3}, {%4,%5,%6,%7}, {%8,%9}, {%0,%1,%2,%3};"
        : "+f"(d[0]), "+f"(d[1]), "+f"(d[2]), "+f"(d[3])
        : "r"(a[0]), "r"(a[1]), "r"(a[2]), "r"(a[3]), "r"(b[0]), "r"(b[1]));
}

// swizzled smem byte offset for (row, 16B-chunk)
__device__ __forceinline__ uint32_t swz(int row, int ch) {
    return (uint32_t)(row * 128 + ((ch ^ (row & 7)) << 4));
}

// ---------------- dequant (exact fp32 fake-quant, round to fp16) ----------------
__device__ __forceinline__ float fq(float v, float s, float z) {
    float q = rintf(v / s + z);             // round half-to-even, matches jnp.round
    q = fminf(fmaxf(q, 0.0f), 255.0f);
    return (q - z) * s;
}

union HalfPack { __half2 h2[2]; uint2 u; };

// Merged dequant: 8 quant blocks/thread, all loads issued before math (MLP ~16-24).
#define DQ_THREADS 256
#define DQ_PER_THREAD 8
#define DQ_PER_CTA (DQ_THREADS * DQ_PER_THREAD)   // 2048

__global__ void __launch_bounds__(DQ_THREADS, 4)
dequant_all_kernel(const float* __restrict__ x,  const float* __restrict__ xs,
                   const float* __restrict__ xz,
                   const float* __restrict__ w,  const float* __restrict__ ws,
                   const float* __restrict__ wz) {
    int j0 = blockIdx.x * DQ_PER_CTA + threadIdx.x;
    float4 v[DQ_PER_THREAD];
    float  s[DQ_PER_THREAD], z[DQ_PER_THREAD];

    if (j0 < NX_BLOCKS) {
#pragma unroll
        for (int u = 0; u < DQ_PER_THREAD; u++) {
            int j = j0 + u * DQ_THREADS;
            v[u] = reinterpret_cast<const float4*>(x)[j];
            int blk = j & (NB - 1);
            s[u] = __ldg(xs + blk);
            z[u] = __ldg(xz + blk);
        }
#pragma unroll
        for (int u = 0; u < DQ_PER_THREAD; u++) {
            HalfPack p;
            p.h2[0] = __floats2half2_rn(fq(v[u].x, s[u], z[u]), fq(v[u].y, s[u], z[u]));
            p.h2[1] = __floats2half2_rn(fq(v[u].z, s[u], z[u]), fq(v[u].w, s[u], z[u]));
            reinterpret_cast<uint2*>(g_Xh)[j0 + u * DQ_THREADS] = p.u;
        }
    } else {
        int k0 = j0 - NX_BLOCKS;
#pragma unroll
        for (int u = 0; u < DQ_PER_THREAD; u++) {
            int k = k0 + u * DQ_THREADS;
            v[u] = reinterpret_cast<const float4*>(w)[k];
            s[u] = __ldg(ws + k);
            z[u] = __ldg(wz + k);
        }
#pragma unroll
        for (int u = 0; u < DQ_PER_THREAD; u++) {
            HalfPack p;
            p.h2[0] = __floats2half2_rn(fq(v[u].x, s[u], z[u]), fq(v[u].y, s[u], z[u]));
            p.h2[1] = __floats2half2_rn(fq(v[u].z, s[u], z[u]), fq(v[u].w, s[u], z[u]));
            reinterpret_cast<uint2*>(g_Wh)[k0 + u * DQ_THREADS] = p.u;
        }
    }
}

// ---------------- stage loader: gmem(fp16) -> smem, 16B cp.async, swizzled ----------------
__device__ __forceinline__ void load_stage(uint32_t sA, uint32_t sB, int m0, int n0, int kc) {
    int t = threadIdx.x;
#pragma unroll
    for (int i = 0; i < 4; i++) {                  // A: 128 rows x 8 chunks = 1024
        int idx = t + i * 256;
        int row = idx >> 3, ch = idx & 7;
        const __half* src = g_Xh + (size_t)(m0 + row) * IN_DIM + kc + ch * 8;
        cp_async16(sA + swz(row, ch), src);
    }
#pragma unroll
    for (int i = 0; i < 8; i++) {                  // B: 256 rows x 8 chunks = 2048
        int idx = t + i * 256;
        int row = idx >> 3, ch = idx & 7;
        const __half* src = g_Wh + (size_t)(n0 + row) * IN_DIM + kc + ch * 8;
        cp_async16(sB + swz(row, ch), src);
    }
}

// ---------------- GEMM: 128x256 tile/CTA, warp 64x64, 4-stage, reg double-buffered ----------------
__global__ void __launch_bounds__(256, 1)
gemm_f16_kernel(const float* __restrict__ bias, float* __restrict__ out) {
    extern __shared__ char smem[];
    uint32_t sbase = smem_u32(smem);
    int tid = threadIdx.x;
    int wid = tid >> 5, lane = tid & 31;
    int m0 = blockIdx.y * BM;
    int n0 = blockIdx.x * BN;
    int wm = (wid & 1) * 64;      // 2 (m) x 4 (n) warps, warp tile 64 x 64
    int wn = (wid >> 1) * 64;

    int lrow = lane & 15;         // ldmatrix x4: lanes 0-15 rows, 16-31 chunk+1
    int lch  = lane >> 4;

    float acc[4][8][4];
#pragma unroll
    for (int i = 0; i < 4; i++)
#pragma unroll
        for (int j = 0; j < 8; j++)
#pragma unroll
            for (int k = 0; k < 4; k++) acc[i][j][k] = 0.0f;

    uint32_t a[2][4][4];          // double-buffered fragments across k-steps
    uint32_t b[2][8][2];

    // prologue: stages 0,1,2
#pragma unroll
    for (int st = 0; st < 3; st++) {
        load_stage(sbase + st * STAGE_BYTES, sbase + st * STAGE_BYTES + A_BYTES,
                   m0, n0, st * BK);
        CP_COMMIT();
    }

#pragma unroll 1
    for (int c = 0; c < NCHUNK; ++c) {
        CP_WAIT(2);               // stage c complete (c+1, c+2 may be in flight)
        __syncthreads();          // all warps done with old slot; stage c visible

        if (c + 3 < NCHUNK) {     // prefetch into slot (c+3)%4
            int st = (c + 3) % STAGES;
            load_stage(sbase + st * STAGE_BYTES, sbase + st * STAGE_BYTES + A_BYTES,
                       m0, n0, (c + 3) * BK);
        }
        CP_COMMIT();

        uint32_t sA = sbase + (c % STAGES) * STAGE_BYTES;
        uint32_t sB = sA + A_BYTES;

        // load fragments for ks=0 into buffer 0
#pragma unroll
        for (int i = 0; i < 4; i++)
            ldmatrix_x4(a[0][i][0], a[0][i][1], a[0][i][2], a[0][i][3],
                        sA + swz(wm + i * 16 + lrow, lch));
#pragma unroll
        for (int j = 0; j < 4; j++) {
            uint32_t r0, r1, r2, r3;
            ldmatrix_x4(r0, r1, r2, r3, sB + swz(wn + j * 16 + lrow, lch));
            b[0][2 * j][0] = r0;     b[0][2 * j][1] = r2;
            b[0][2 * j + 1][0] = r1; b[0][2 * j + 1][1] = r3;
        }

#pragma unroll
        for (int ks = 0; ks < 4; ks++) {          // 4 x k16 per BK=64
            int cur = ks & 1, nxt = cur ^ 1;
            if (ks < 3) {                          // prefetch frags for ks+1
#pragma unroll
                for (int i = 0; i < 4; i++)
                    ldmatrix_x4(a[nxt][i][0], a[nxt][i][1], a[nxt][i][2], a[nxt][i][3],
                                sA + swz(wm + i * 16 + lrow, (ks + 1) * 2 + lch));
#pragma unroll
                for (int j = 0; j < 4; j++) {
                    uint32_t r0, r1, r2, r3;
                    ldmatrix_x4(r0, r1, r2, r3,
                                sB + swz(wn + j * 16 + lrow, (ks + 1) * 2 + lch));
                    b[nxt][2 * j][0] = r0;     b[nxt][2 * j][1] = r2;
                    b[nxt][2 * j + 1][0] = r1; b[nxt][2 * j + 1][1] = r3;
                }
            }
#pragma unroll
            for (int i = 0; i < 4; i++)
#pragma unroll
                for (int j = 0; j < 8; j++)
                    mma16816(acc[i][j], a[cur][i], b[cur][j]);
        }
    }

    // epilogue: C frag -> gmem with bias. lane: g = lane/4 (row), c2 = (lane%4)*2 (col)
    int g = lane >> 2, c2 = (lane & 3) * 2;
#pragma unroll
    for (int i = 0; i < 4; i++) {
        int row = m0 + wm + i * 16 + g;
        float* r0p = out + (size_t)row * OUT_DIM;
        float* r1p = out + (size_t)(row + 8) * OUT_DIM;
#pragma unroll
        for (int j = 0; j < 8; j++) {
            int col = n0 + wn + j * 8 + c2;
            float b0 = __ldg(&bias[col]), b1 = __ldg(&bias[col + 1]);
            float2 v0 = make_float2(acc[i][j][0] + b0, acc[i][j][1] + b1);
            float2 v1 = make_float2(acc[i][j][2] + b0, acc[i][j][3] + b1);
            *reinterpret_cast<float2*>(r0p + col) = v0;
            *reinterpret_cast<float2*>(r1p + col) = v1;
        }
    }
}

// ---------------- launch ----------------
extern "C" void kernel_launch(void* const* d_in, const int* in_sizes, int n_in,
                              void* d_out, int out_size) {
    const float* x    = (const float*)d_in[0];
    const float* w    = (const float*)d_in[1];
    const float* bias = (const float*)d_in[2];
    const float* ws   = (const float*)d_in[3];
    const float* wz   = (const float*)d_in[4];
    const float* as_  = (const float*)d_in[5];
    const float* az   = (const float*)d_in[6];
    float* out = (float*)d_out;

    dequant_all_kernel<<<NT_BLOCKS / DQ_PER_CTA, DQ_THREADS>>>(x, as_, az, w, ws, wz);

    cudaFuncSetAttribute(gemm_f16_kernel, cudaFuncAttributeMaxDynamicSharedMemorySize, SMEM_TOTAL);
    dim3 grid(OUT_DIM / BN, B_DIM / BM);   // 16 x 8 = 128 CTAs, one wave
    gemm_f16_kernel<<<grid, 256, SMEM_TOTAL>>>(bias, out);
}

// round 7
// speedup vs baseline: 1.0537x; 1.0033x over previous
#include <cuda_runtime.h>
#include <cuda_fp16.h>
#include <cstdint>

// ---------------- problem dims (fixed) ----------------
#define B_DIM   1024
#define IN_DIM  4096
#define OUT_DIM 4096
#define NB      1024          // IN_DIM / 4 quant blocks per row
#define NX_BLOCKS (B_DIM * NB)      // 1,048,576  (x quant blocks)
#define NW_BLOCKS (OUT_DIM * NB)    // 4,194,304  (w quant blocks)
#define NT_BLOCKS (NX_BLOCKS + NW_BLOCKS)

// ---------------- GEMM tiling ----------------
#define BM 128
#define BN 256
#define BK 64                  // fine chunk: 128 bytes per smem row
#define BIG 128                // coarse stage = 2 fine chunks
#define NITER (IN_DIM / BIG)   // 32
#define A_BYTES (BM * 128)                    // 16 KB per fine chunk
#define B_BYTES (BN * 128)                    // 32 KB per fine chunk
#define CHUNK_BYTES (A_BYTES + B_BYTES)       // 48 KB
#define STAGE_BYTES (2 * CHUNK_BYTES)         // 96 KB coarse stage
#define SMEM_TOTAL (2 * STAGE_BYTES)          // 192 KB, 2 coarse stages

// ---------------- fp16 dequant scratch (device globals: allocation-free) ----------------
__device__ __half g_Xh[(size_t)B_DIM * IN_DIM];    // 8 MB
__device__ __half g_Wh[(size_t)OUT_DIM * IN_DIM];  // 32 MB

// ---------------- helpers ----------------
__device__ __forceinline__ uint32_t smem_u32(const void* p) {
    uint32_t a;
    asm("{ .reg .u64 t; cvta.to.shared.u64 t, %1; cvt.u32.u64 %0, t; }" : "=r"(a) : "l"(p));
    return a;
}

__device__ __forceinline__ void cp_async16(uint32_t dst, const void* src) {
    asm volatile("cp.async.cg.shared.global [%0], [%1], 16;" :: "r"(dst), "l"(src) : "memory");
}
#define CP_COMMIT() asm volatile("cp.async.commit_group;" ::: "memory")
#define CP_WAIT(n)  asm volatile("cp.async.wait_group %0;" :: "n"(n) : "memory")

__device__ __forceinline__ void ldmatrix_x4(uint32_t& r0, uint32_t& r1, uint32_t& r2, uint32_t& r3,
                                            uint32_t addr) {
    asm volatile("ldmatrix.sync.aligned.m8n8.x4.shared.b16 {%0,%1,%2,%3}, [%4];"
                 : "=r"(r0), "=r"(r1), "=r"(r2), "=r"(r3) : "r"(addr));
}

__device__ __forceinline__ void mma16816(float* d, const uint32_t* a, const uint32_t* b) {
    asm volatile(
        "mma.sync.aligned.m16n8k16.row.col.f32.f16.f16.f32 "
        "{%0,%1,%2,%3}, {%4,%5,%6,%7}, {%8,%9}, {%0,%1,%2,%3};"
        : "+f"(d[0]), "+f"(d[1]), "+f"(d[2]), "+f"(d[3])
        : "r"(a[0]), "r"(a[1]), "r"(a[2]), "r"(a[3]), "r"(b[0]), "r"(b[1]));
}

// swizzled smem byte offset for (row, 16B-chunk)
__device__ __forceinline__ uint32_t swz(int row, int ch) {
    return (uint32_t)(row * 128 + ((ch ^ (row & 7)) << 4));
}

// ---------------- dequant (exact fp32 fake-quant, round to fp16) ----------------
__device__ __forceinline__ float fq(float v, float s, float z) {
    float q = rintf(v / s + z);             // round half-to-even, matches jnp.round
    q = fminf(fmaxf(q, 0.0f), 255.0f);
    return (q - z) * s;
}

union HalfPack { __half2 h2[2]; uint2 u; };

// Merged dequant: 8 quant blocks/thread, all loads issued before math (MLP ~16-24).
#define DQ_THREADS 256
#define DQ_PER_THREAD 8
#define DQ_PER_CTA (DQ_THREADS * DQ_PER_THREAD)   // 2048

__global__ void __launch_bounds__(DQ_THREADS, 4)
dequant_all_kernel(const float* __restrict__ x,  const float* __restrict__ xs,
                   const float* __restrict__ xz,
                   const float* __restrict__ w,  const float* __restrict__ ws,
                   const float* __restrict__ wz) {
    int j0 = blockIdx.x * DQ_PER_CTA + threadIdx.x;
    float4 v[DQ_PER_THREAD];
    float  s[DQ_PER_THREAD], z[DQ_PER_THREAD];

    if (j0 < NX_BLOCKS) {
#pragma unroll
        for (int u = 0; u < DQ_PER_THREAD; u++) {
            int j = j0 + u * DQ_THREADS;
            v[u] = reinterpret_cast<const float4*>(x)[j];
            int blk = j & (NB - 1);
            s[u] = __ldg(xs + blk);
            z[u] = __ldg(xz + blk);
        }
#pragma unroll
        for (int u = 0; u < DQ_PER_THREAD; u++) {
            HalfPack p;
            p.h2[0] = __floats2half2_rn(fq(v[u].x, s[u], z[u]), fq(v[u].y, s[u], z[u]));
            p.h2[1] = __floats2half2_rn(fq(v[u].z, s[u], z[u]), fq(v[u].w, s[u], z[u]));
            reinterpret_cast<uint2*>(g_Xh)[j0 + u * DQ_THREADS] = p.u;
        }
    } else {
        int k0 = j0 - NX_BLOCKS;
#pragma unroll
        for (int u = 0; u < DQ_PER_THREAD; u++) {
            int k = k0 + u * DQ_THREADS;
            v[u] = reinterpret_cast<const float4*>(w)[k];
            s[u] = __ldg(ws + k);
            z[u] = __ldg(wz + k);
        }
#pragma unroll
        for (int u = 0; u < DQ_PER_THREAD; u++) {
            HalfPack p;
            p.h2[0] = __floats2half2_rn(fq(v[u].x, s[u], z[u]), fq(v[u].y, s[u], z[u]));
            p.h2[1] = __floats2half2_rn(fq(v[u].z, s[u], z[u]), fq(v[u].w, s[u], z[u]));
            reinterpret_cast<uint2*>(g_Wh)[k0 + u * DQ_THREADS] = p.u;
        }
    }
}

// ---------------- fine-chunk loader: gmem(fp16) -> smem, 16B cp.async, swizzled ----------------
__device__ __forceinline__ void load_chunk(uint32_t sA, uint32_t sB, int m0, int n0, int kc) {
    int t = threadIdx.x;
#pragma unroll
    for (int i = 0; i < 4; i++) {                  // A: 128 rows x 8 chunks = 1024
        int idx = t + i * 256;
        int row = idx >> 3, ch = idx & 7;
        const __half* src = g_Xh + (size_t)(m0 + row) * IN_DIM + kc + ch * 8;
        cp_async16(sA + swz(row, ch), src);
    }
#pragma unroll
    for (int i = 0; i < 8; i++) {                  // B: 256 rows x 8 chunks = 2048
        int idx = t + i * 256;
        int row = idx >> 3, ch = idx & 7;
        const __half* src = g_Wh + (size_t)(n0 + row) * IN_DIM + kc + ch * 8;
        cp_async16(sB + swz(row, ch), src);
    }
}

// coarse stage = 2 fine chunks laid back-to-back
__device__ __forceinline__ void load_stage(uint32_t slot, int m0, int n0, int kc) {
    load_chunk(slot, slot + A_BYTES, m0, n0, kc);
    load_chunk(slot + CHUNK_BYTES, slot + CHUNK_BYTES + A_BYTES, m0, n0, kc + BK);
}

// ---------------- GEMM: 128x256 tile/CTA, warp 64x64, coarse double buffer ----------------
__global__ void __launch_bounds__(256, 1)
gemm_f16_kernel(const float* __restrict__ bias, float* __restrict__ out) {
    extern __shared__ char smem[];
    uint32_t sbase = smem_u32(smem);
    int tid = threadIdx.x;
    int wid = tid >> 5, lane = tid & 31;
    int m0 = blockIdx.y * BM;
    int n0 = blockIdx.x * BN;
    int wm = (wid & 1) * 64;      // 2 (m) x 4 (n) warps, warp tile 64 x 64
    int wn = (wid >> 1) * 64;

    int lrow = lane & 15;         // ldmatrix x4: lanes 0-15 rows, 16-31 chunk+1
    int lch  = lane >> 4;

    float acc[4][8][4];
#pragma unroll
    for (int i = 0; i < 4; i++)
#pragma unroll
        for (int j = 0; j < 8; j++)
#pragma unroll
            for (int k = 0; k < 4; k++) acc[i][j][k] = 0.0f;

    // prologue: coarse stage 0
    load_stage(sbase, m0, n0, 0);
    CP_COMMIT();

#pragma unroll 1
    for (int c = 0; c < NITER; ++c) {
        CP_WAIT(0);               // my copies for stage c retired
        __syncthreads();          // everyone's copies visible; stage c-1 fully consumed

        if (c + 1 < NITER) {      // overwrite the slot stage c-1 occupied
            load_stage(sbase + ((c + 1) & 1) * STAGE_BYTES, m0, n0, (c + 1) * BIG);
            CP_COMMIT();
        }

        uint32_t slot = sbase + (c & 1) * STAGE_BYTES;

#pragma unroll
        for (int sub = 0; sub < 2; sub++) {       // 2 fine chunks per coarse stage
            uint32_t sA = slot + sub * CHUNK_BYTES;
            uint32_t sB = sA + A_BYTES;
#pragma unroll
            for (int ks = 0; ks < 4; ks++) {      // 4 x k16 per fine chunk
                uint32_t a[4][4];
#pragma unroll
                for (int i = 0; i < 4; i++) {
                    int row = wm + i * 16 + lrow;
                    ldmatrix_x4(a[i][0], a[i][1], a[i][2], a[i][3],
                                sA + swz(row, ks * 2 + lch));
                }
                uint32_t b[8][2];
#pragma unroll
                for (int j = 0; j < 4; j++) {
                    int row = wn + j * 16 + lrow;
                    uint32_t r0, r1, r2, r3;
                    ldmatrix_x4(r0, r1, r2, r3, sB + swz(row, ks * 2 + lch));
                    b[2 * j][0] = r0;     b[2 * j][1] = r2;      // n-tile rows +0..7
                    b[2 * j + 1][0] = r1; b[2 * j + 1][1] = r3;  // n-tile rows +8..15
                }
#pragma unroll
                for (int i = 0; i < 4; i++)
#pragma unroll
                    for (int j = 0; j < 8; j++)
                        mma16816(acc[i][j], a[i], b[j]);
            }
        }
    }

    // epilogue: C frag -> gmem with bias. lane: g = lane/4 (row), c2 = (lane%4)*2 (col)
    int g = lane >> 2, c2 = (lane & 3) * 2;
#pragma unroll
    for (int i = 0; i < 4; i++) {
        int row = m0 + wm + i * 16 + g;
        float* r0p = out + (size_t)row * OUT_DIM;
        float* r1p = out + (size_t)(row + 8) * OUT_DIM;
#pragma unroll
        for (int j = 0; j < 8; j++) {
            int col = n0 + wn + j * 8 + c2;
            float b0 = __ldg(&bias[col]), b1 = __ldg(&bias[col + 1]);
            float2 v0 = make_float2(acc[i][j][0] + b0, acc[i][j][1] + b1);
            float2 v1 = make_float2(acc[i][j][2] + b0, acc[i][j][3] + b1);
            *reinterpret_cast<float2*>(r0p + col) = v0;
            *reinterpret_cast<float2*>(r1p + col) = v1;
        }
    }
}

// ---------------- launch ----------------
extern "C" void kernel_launch(void* const* d_in, const int* in_sizes, int n_in,
                              void* d_out, int out_size) {
    const float* x    = (const float*)d_in[0];
    const float* w    = (const float*)d_in[1];
    const float* bias = (const float*)d_in[2];
    const float* ws   = (const float*)d_in[3];
    const float* wz   = (const float*)d_in[4];
    const float* as_  = (const float*)d_in[5];
    const float* az   = (const float*)d_in[6];
    float* out = (float*)d_out;

    dequant_all_kernel<<<NT_BLOCKS / DQ_PER_CTA, DQ_THREADS>>>(x, as_, az, w, ws, wz);

    cudaFuncSetAttribute(gemm_f16_kernel, cudaFuncAttributeMaxDynamicSharedMemorySize, SMEM_TOTAL);
    dim3 grid(OUT_DIM / BN, B_DIM / BM);   // 16 x 8 = 128 CTAs, one wave
    gemm_f16_kernel<<<grid, 256, SMEM_TOTAL>>>(bias, out);
}